// round 16
// baseline (speedup 1.0000x reference)
#include <cuda_runtime.h>

#define FULL 0xFFFFFFFFu

__device__ __forceinline__ unsigned long long pack2(float a, float b) {
    unsigned long long r;
    asm("mov.b64 %0, {%1, %2};" : "=l"(r) : "f"(a), "f"(b));
    return r;
}
__device__ __forceinline__ void unpack2(unsigned long long p, float& a, float& b) {
    asm("mov.b64 {%0, %1}, %2;" : "=f"(a), "=f"(b) : "l"(p));
}
__device__ __forceinline__ unsigned long long fma2(unsigned long long a,
                                                   unsigned long long b,
                                                   unsigned long long c) {
    unsigned long long d;
    asm("fma.rn.f32x2 %0, %1, %2, %3;" : "=l"(d) : "l"(a), "l"(b), "l"(c));
    return d;
}
__device__ __forceinline__ unsigned long long add2(unsigned long long a,
                                                   unsigned long long b) {
    unsigned long long d;
    asm("add.rn.f32x2 %0, %1, %2;" : "=l"(d) : "l"(a), "l"(b));
    return d;
}
__device__ __forceinline__ float tanh_ap(float x) {
    float r; asm("tanh.approx.f32 %0, %1;" : "=f"(r) : "f"(x)); return r;
}
// sigma from half-scaled argument zh = z/2 :  0.5*tanh(zh) + 0.5
__device__ __forceinline__ float sigmoid_half(float zh) {
    return fmaf(0.5f, tanh_ap(zh), 0.5f);
}

// One CTA per TWO batches, 288 threads, grid 128 (one CTA/SM, single wave).
// Round 16: the per-step fma burst is split across TWO layer-0 warps per
// SMSP. R15 closed its cycle budget on per-warp issue serialization: one
// warp issuing 128 fma2 at stall=2 needs 256 cycles all by itself. Warps
// 0-3 handle batch 0, warps 4-7 batch 1 (wid%4 -> one warp of each batch
// per SMSP); each thread now does 64 fma2 + 8 LDS (one batch), so per-warp
// issue is ~140 cycles and the two warps interleave to keep the fma pipe at
// its 256-cycle floor while covering each other's LDS/tail/BAR latency.
// Unlike R6 (which failed this shape), the tail is now 5 MUFU.TANH per warp
// (80 cyc MUFU pipe per SMSP for 2 warps, far from binding) instead of 24
// EX2/RCP (192 cyc, the real R6 killer).
// Thread (u = (tid&127)>>1, k = tid&1) owns all 4 gate columns of unit u,
// K-half k, batch tid>>7. 4 shfl_xor combine K-halves (both lanes get
// bitwise-identical z); redundant lane-pair tail; k==0 stores h.
// Warp 8: layer-1 (units=1) + dense for both batches (lane halves), one
// step lagged. One __syncthreads per step. Depth-1 LDS pipeline kept.
__global__ __launch_bounds__(288, 1)
void lstm_stack_kernel(const float* __restrict__ x,
                       const float* __restrict__ W0,
                       const float* __restrict__ b0,
                       const float* __restrict__ W1,
                       const float* __restrict__ b1,
                       const float* __restrict__ Wd,
                       const float* __restrict__ bd,
                       float* __restrict__ out)
{
    constexpr int T = 2048;
    constexpr int HP = 72;            // padded h row (bank-conflict-free STS)

    const int bb   = blockIdx.x;      // batch pair
    const int tid  = threadIdx.x;
    const int lane = tid & 31;
    const int wid  = tid >> 5;

    __shared__ __align__(16) float x_sh[2][T];
    __shared__ __align__(16) float h_sh[2][2][HP];   // [buffer][batch][unit(+pad)]
    __shared__ float red[9];
    __shared__ float inv_sh[2];

    // ---- Phase 0: load both x tiles, l2-normalize over time ----
    for (int bi = 0; bi < 2; ++bi) {
        const float* xb = x + (2 * bb + bi) * T;
        float ps = 0.f;
        for (int i = tid; i < T; i += 288) {
            float v = xb[i];
            x_sh[bi][i] = v;
            ps = fmaf(v, v, ps);
        }
        #pragma unroll
        for (int o = 16; o > 0; o >>= 1) ps += __shfl_xor_sync(FULL, ps, o);
        if (lane == 0) red[wid] = ps;
        __syncthreads();
        if (tid == 0) {
            float s = 0.f;
            #pragma unroll
            for (int i = 0; i < 9; ++i) s += red[i];
            inv_sh[bi] = rsqrtf(fmaxf(s, 1e-12f));
        }
        __syncthreads();               // also protects red[] reuse
    }
    {
        float i0 = inv_sh[0], i1 = inv_sh[1];
        for (int i = tid; i < T; i += 288) {
            x_sh[0][i] *= i0;
            x_sh[1][i] *= i1;
        }
    }
    if (tid < 2 * HP) ((float*)h_sh[0])[tid] = 0.f;   // h_{-1} = 0 (both batches)
    // (ordered by the first __syncthreads in the main sequence)

    // ---- Per-thread persistent state / weights ----
    const int w128 = tid & 127;
    const int bsel = (tid >> 7) & 1;    // batch: warps 0-3 -> 0, 4-7 -> 1
    const int u = w128 >> 1;
    const int k = w128 & 1;             // K-half
    unsigned long long wf[4][16];       // [gate][pair within my K-half]
    float wxe[4], bze[4];               // x-weight / bias seeds (0 on k=1)
    float c0 = 0.f;                     // cell state (redundant in lane pair)

    // layer-1 (warp 8) state: lanes 0-15 -> batch0, 16-31 -> batch1
    const int l1b  = lane >> 4;
    const int l1g  = lane & 3;
    const int l1bk = (lane >> 2) & 3;
    float w1r[16];
    float w1h = 0.f, b1v = 0.f, wdv = 0.f, bdv = 0.f;
    float c1 = 0.f, h1 = 0.f;

    if (tid < 256) {
        #pragma unroll
        for (int g = 0; g < 4; ++g) {
            // i/f/o: fold sigma's 1/2 into the column; j: unscaled (tanh direct)
            const float sc = (g == 1) ? 1.0f : 0.5f;
            const int col = g * 64 + u;
            wxe[g] = (k == 0) ? (W0[col] * sc) : 0.f;
            bze[g] = (k == 0) ? ((b0[col] + (g == 2 ? 1.0f : 0.0f)) * sc) : 0.f;
            #pragma unroll
            for (int p = 0; p < 16; ++p) {
                const int row = 1 + 32 * k + 2 * p;
                wf[g][p] = pack2(W0[row * 256 + col] * sc,
                                 W0[(row + 1) * 256 + col] * sc);
            }
        }
    } else {
        #pragma unroll
        for (int j = 0; j < 16; ++j)
            w1r[j] = W1[(l1bk + 4 * j) * 4 + l1g];
        w1h = W1[64 * 4 + l1g];
        b1v = b1[l1g];
        wdv = Wd[0];
        bdv = bd[0];
    }

    // ---- Step bodies ----
    auto layer0_step = [&](int t) {
        const int cur = t & 1;
        const float xt = x_sh[bsel][t];
        const ulonglong2* hp = (const ulonglong2*)&h_sh[cur][bsel][k * 32];
        // 8 accumulator chains: [gate] x {x-chain, y-chain}, one batch
        unsigned long long ax[4], ay[4];
        #pragma unroll
        for (int g = 0; g < 4; ++g) {
            ax[g] = pack2(fmaf(xt, wxe[g], bze[g]), 0.f);
            ay[g] = pack2(0.f, 0.f);
        }
        // depth-1 software pipeline on the h LDS
        ulonglong2 hv = hp[0];
        #pragma unroll
        for (int i = 0; i < 8; ++i) {
            ulonglong2 nv;
            if (i < 7) nv = hp[i + 1];
            #pragma unroll
            for (int g = 0; g < 4; ++g) {
                ax[g] = fma2(hv.x, wf[g][2 * i],     ax[g]);
                ay[g] = fma2(hv.y, wf[g][2 * i + 1], ay[g]);
            }
            if (i < 7) hv = nv;
        }
        // partial z per gate, then combine K-halves (one shfl per gate;
        // both lanes end with bitwise-identical z[g])
        float z[4];
        #pragma unroll
        for (int g = 0; g < 4; ++g) {
            float lo, hi;
            unpack2(add2(ax[g], ay[g]), lo, hi);
            float P = lo + hi;
            z[g] = P + __shfl_xor_sync(FULL, P, 1);
        }
        // redundant lane-pair tail via HW tanh
        float si = sigmoid_half(z[0]);       // z pre-halved via weights
        float tj = tanh_ap(z[1]);            // j unscaled -> tanh direct
        float sf = sigmoid_half(z[2]);       // forget bias folded
        float so = sigmoid_half(z[3]);
        c0 = fmaf(sf, c0, si * tj);
        float hval = so * tanh_ap(c0);
        if (k == 0) h_sh[cur ^ 1][bsel][u] = hval;
    };

    auto layer1_step = [&](int s) {          // computes layer-1 step s
        const int buf = (s + 1) & 1;         // h_sh[buf] holds h^{(0)}(s)
        const float* hv = h_sh[buf][l1b];
        float p0 = 0.f, p1 = 0.f;
        #pragma unroll
        for (int j = 0; j < 8; ++j) {
            p0 = fmaf(hv[l1bk + 4 * (2 * j)],     w1r[2 * j],     p0);
            p1 = fmaf(hv[l1bk + 4 * (2 * j + 1)], w1r[2 * j + 1], p1);
        }
        float p = p0 + p1;
        p += __shfl_xor_sync(FULL, p, 4);    // stays within 16-lane half
        p += __shfl_xor_sync(FULL, p, 8);
        float z1 = fmaf(h1, w1h, p + b1v);

        float zz = (l1g == 2) ? (z1 + 1.0f) : z1;
        // gate: j -> tanh(z); i/f/o -> sigma(z) = 0.5*tanh(z/2)+0.5
        float r = (l1g == 1) ? tanh_ap(zz)
                             : fmaf(0.5f, tanh_ap(0.5f * zz), 0.5f);

        float ri = __shfl_sync(FULL, r, 0, 4);
        float rj = __shfl_sync(FULL, r, 1, 4);
        float rf = __shfl_sync(FULL, r, 2, 4);
        float ro = __shfl_sync(FULL, r, 3, 4);
        c1 = fmaf(rf, c1, ri * rj);
        h1 = ro * tanh_ap(c1);
        if ((lane & 15) == 0)
            out[(2 * bb + l1b) * T + s] = fmaf(h1, wdv, bdv);
    };

    // ---- Peeled main sequence ----
    __syncthreads();                      // orders phase-0 writes + h init
    if (tid < 256) layer0_step(0);
    #pragma unroll 1
    for (int t = 1; t < T; ++t) {
        __syncthreads();                  // publishes h(t-1)
        if (tid < 256) layer0_step(t);
        else           layer1_step(t - 1);
    }
    __syncthreads();                      // publishes h(T-1)
    if (tid >= 256) layer1_step(T - 1);   // drain
}

extern "C" void kernel_launch(void* const* d_in, const int* in_sizes, int n_in,
                              void* d_out, int out_size) {
    const float* x  = (const float*)d_in[0];
    const float* W0 = (const float*)d_in[1];
    const float* b0 = (const float*)d_in[2];
    const float* W1 = (const float*)d_in[3];
    const float* b1 = (const float*)d_in[4];
    const float* Wd = (const float*)d_in[5];
    const float* bd = (const float*)d_in[6];
    float* out = (float*)d_out;
    lstm_stack_kernel<<<128, 288>>>(x, W0, b0, W1, b1, Wd, bd, out);
}

// round 17
// speedup vs baseline: 1.0309x; 1.0309x over previous
#include <cuda_runtime.h>

#define FULL 0xFFFFFFFFu

__device__ __forceinline__ unsigned long long pack2(float a, float b) {
    unsigned long long r;
    asm("mov.b64 %0, {%1, %2};" : "=l"(r) : "f"(a), "f"(b));
    return r;
}
__device__ __forceinline__ void unpack2(unsigned long long p, float& a, float& b) {
    asm("mov.b64 {%0, %1}, %2;" : "=f"(a), "=f"(b) : "l"(p));
}
__device__ __forceinline__ unsigned long long fma2(unsigned long long a,
                                                   unsigned long long b,
                                                   unsigned long long c) {
    unsigned long long d;
    asm("fma.rn.f32x2 %0, %1, %2, %3;" : "=l"(d) : "l"(a), "l"(b), "l"(c));
    return d;
}
__device__ __forceinline__ unsigned long long add2(unsigned long long a,
                                                   unsigned long long b) {
    unsigned long long d;
    asm("add.rn.f32x2 %0, %1, %2;" : "=l"(d) : "l"(a), "l"(b));
    return d;
}
__device__ __forceinline__ float tanh_ap(float x) {
    float r; asm("tanh.approx.f32 %0, %1;" : "=f"(r) : "f"(x)); return r;
}
// sigma from half-scaled argument zh = z/2 :  0.5*tanh(zh) + 0.5
__device__ __forceinline__ float sigmoid_half(float zh) {
    return fmaf(0.5f, tanh_ap(zh), 0.5f);
}

// One CTA per TWO batches, 160 threads, grid 128 (one CTA/SM, single wave).
// Round 17: GATES-OUTER + WOVEN TAILS. The FFMA2 burst issues at rt=3
// (3 distinct even-bank registers: h.lo/w.lo/acc.lo), leaving ~1/3 of issue
// slots free inside the burst. The champion's gates-inner loop finished all
// four gate chains simultaneously, so the ~95-cycle nonlinear tail ran fully
// exposed after the burst. Now gates are processed sequentially (j,i,f,o;
// 32 fma2 each) with each finished gate's combine/shfl/MUFU woven into the
// next gate's burst in source order; the c-update chain sits inside gate-o's
// split burst. Only gate-o's ~60-cycle tail remains exposed. All 16 h
// LDS.128 are front-loaded (max MLP). Arithmetic bitwise identical to R15.
// Thread (u = tid>>1, k = tid&1) owns all 4 gate columns of unit u, K-half
// k; 4 shfl_xor combine K-halves (each lane ends with its own batch's z);
// lane-parallel tail (lane k = batch k); sigma's 1/2 pre-folded into i/f/o
// weights. Warp 4: layer-1 + dense for both batches (lane halves), one step
// lagged. One __syncthreads per step.
__global__ __launch_bounds__(160, 1)
void lstm_stack_kernel(const float* __restrict__ x,
                       const float* __restrict__ W0,
                       const float* __restrict__ b0,
                       const float* __restrict__ W1,
                       const float* __restrict__ b1,
                       const float* __restrict__ Wd,
                       const float* __restrict__ bd,
                       float* __restrict__ out)
{
    constexpr int T = 2048;
    constexpr int HP = 72;            // padded h row (bank-conflict-free STS)

    const int bb   = blockIdx.x;      // batch pair
    const int tid  = threadIdx.x;
    const int lane = tid & 31;
    const int wid  = tid >> 5;

    __shared__ __align__(16) float x_sh[2][T];
    __shared__ __align__(16) float h_sh[2][2][HP];   // [buffer][batch][unit(+pad)]
    __shared__ float red[5];
    __shared__ float inv_sh[2];

    // ---- Phase 0: load both x tiles, l2-normalize over time ----
    for (int bi = 0; bi < 2; ++bi) {
        const float* xb = x + (2 * bb + bi) * T;
        float ps = 0.f;
        for (int i = tid; i < T; i += 160) {
            float v = xb[i];
            x_sh[bi][i] = v;
            ps = fmaf(v, v, ps);
        }
        #pragma unroll
        for (int o = 16; o > 0; o >>= 1) ps += __shfl_xor_sync(FULL, ps, o);
        if (lane == 0) red[wid] = ps;
        __syncthreads();
        if (tid == 0) {
            float s = 0.f;
            #pragma unroll
            for (int i = 0; i < 5; ++i) s += red[i];
            inv_sh[bi] = rsqrtf(fmaxf(s, 1e-12f));
        }
        __syncthreads();               // also protects red[] reuse
    }
    {
        float i0 = inv_sh[0], i1 = inv_sh[1];
        for (int i = tid; i < T; i += 160) {
            x_sh[0][i] *= i0;
            x_sh[1][i] *= i1;
        }
    }
    if (tid < 2 * HP) ((float*)h_sh[0])[tid] = 0.f;   // h_{-1} = 0 (both batches)
    // (ordered by the first __syncthreads in the main sequence)

    // ---- Per-thread persistent state / weights ----
    const int u = tid >> 1;
    const int k = tid & 1;              // K-half AND owned batch for the tail
    unsigned long long wf[4][16];       // [gate][pair within my K-half]
    float wxe[4], bze[4];               // x-weight / bias seeds (0 on k=1)
    float c0 = 0.f;                     // cell state of MY batch (k)

    // layer-1 (warp 4) state: lanes 0-15 -> batch0, 16-31 -> batch1
    const int l1b  = lane >> 4;
    const int l1g  = lane & 3;
    const int l1bk = (lane >> 2) & 3;
    float w1r[16];
    float w1h = 0.f, b1v = 0.f, wdv = 0.f, bdv = 0.f;
    float c1 = 0.f, h1 = 0.f;

    if (tid < 128) {
        #pragma unroll
        for (int g = 0; g < 4; ++g) {
            // i/f/o: fold sigma's 1/2 into the column; j: unscaled (tanh direct)
            const float sc = (g == 1) ? 1.0f : 0.5f;
            const int col = g * 64 + u;
            wxe[g] = (k == 0) ? (W0[col] * sc) : 0.f;
            bze[g] = (k == 0) ? ((b0[col] + (g == 2 ? 1.0f : 0.0f)) * sc) : 0.f;
            #pragma unroll
            for (int p = 0; p < 16; ++p) {
                const int row = 1 + 32 * k + 2 * p;
                wf[g][p] = pack2(W0[row * 256 + col] * sc,
                                 W0[(row + 1) * 256 + col] * sc);
            }
        }
    } else {
        #pragma unroll
        for (int j = 0; j < 16; ++j)
            w1r[j] = W1[(l1bk + 4 * j) * 4 + l1g];
        w1h = W1[64 * 4 + l1g];
        b1v = b1[l1g];
        wdv = Wd[0];
        bdv = bd[0];
    }

    // ---- Step bodies ----
    auto layer0_step = [&](int t) {
        const int cur = t & 1;
        const float xt0 = x_sh[0][t];
        const float xt1 = x_sh[1][t];
        const ulonglong2* hp0 = (const ulonglong2*)&h_sh[cur][0][k * 32];
        const ulonglong2* hp1 = (const ulonglong2*)&h_sh[cur][1][k * 32];

        // front-load ALL h (16 LDS.128, max MLP; latency covered by gate-j)
        ulonglong2 H0[8], H1[8];
        #pragma unroll
        for (int i = 0; i < 8; ++i) H0[i] = hp0[i];
        #pragma unroll
        for (int i = 0; i < 8; ++i) H1[i] = hp1[i];

        // per-gate chains: 32 fma2 (both batches), then combine to partials
        #define GATE_DOT(g, P0v, P1v)                                        \
        {                                                                    \
            unsigned long long ax0 = pack2(fmaf(xt0, wxe[g], bze[g]), 0.f);  \
            unsigned long long ay0 = pack2(0.f, 0.f);                        \
            unsigned long long ax1 = pack2(fmaf(xt1, wxe[g], bze[g]), 0.f);  \
            unsigned long long ay1 = pack2(0.f, 0.f);                        \
            _Pragma("unroll")                                                \
            for (int i = 0; i < 8; ++i) {                                    \
                ax0 = fma2(H0[i].x, wf[g][2 * i],     ax0);                  \
                ay0 = fma2(H0[i].y, wf[g][2 * i + 1], ay0);                  \
                ax1 = fma2(H1[i].x, wf[g][2 * i],     ax1);                  \
                ay1 = fma2(H1[i].y, wf[g][2 * i + 1], ay1);                  \
            }                                                                \
            float lo, hi;                                                    \
            unpack2(add2(ax0, ay0), lo, hi); P0v = lo + hi;                  \
            unpack2(add2(ax1, ay1), lo, hi); P1v = lo + hi;                  \
        }

        // ---- gate j (tanh input) ----
        float Pj0, Pj1;
        GATE_DOT(1, Pj0, Pj1);
        float oj = k ? Pj1 : Pj0;
        float rj = __shfl_xor_sync(FULL, k ? Pj0 : Pj1, 1);

        // ---- gate i (shfl_j latency hides under this burst) ----
        float Pi0, Pi1;
        GATE_DOT(0, Pi0, Pi1);
        float tj = tanh_ap(oj + rj);             // MUFU launches inside burst
        float oi = k ? Pi1 : Pi0;
        float ri = __shfl_xor_sync(FULL, k ? Pi0 : Pi1, 1);

        // ---- gate f (tj + shfl_i hide under this burst) ----
        float Pf0, Pf1;
        GATE_DOT(2, Pf0, Pf1);
        float si = sigmoid_half(oi + ri);
        float of = k ? Pf1 : Pf0;
        float rf = __shfl_xor_sync(FULL, k ? Pf0 : Pf1, 1);
        float pij = si * tj;

        // ---- gate o, first half; c-chain woven between the halves ----
        unsigned long long ax0 = pack2(fmaf(xt0, wxe[3], bze[3]), 0.f);
        unsigned long long ay0 = pack2(0.f, 0.f);
        unsigned long long ax1 = pack2(fmaf(xt1, wxe[3], bze[3]), 0.f);
        unsigned long long ay1 = pack2(0.f, 0.f);
        #pragma unroll
        for (int i = 0; i < 4; ++i) {
            ax0 = fma2(H0[i].x, wf[3][2 * i],     ax0);
            ay0 = fma2(H0[i].y, wf[3][2 * i + 1], ay0);
            ax1 = fma2(H1[i].x, wf[3][2 * i],     ax1);
            ay1 = fma2(H1[i].y, wf[3][2 * i + 1], ay1);
        }
        float sf = sigmoid_half(of + rf);
        c0 = fmaf(sf, c0, pij);
        float thc = tanh_ap(c0);                 // hides under second half
        #pragma unroll
        for (int i = 4; i < 8; ++i) {
            ax0 = fma2(H0[i].x, wf[3][2 * i],     ax0);
            ay0 = fma2(H0[i].y, wf[3][2 * i + 1], ay0);
            ax1 = fma2(H1[i].x, wf[3][2 * i],     ax1);
            ay1 = fma2(H1[i].y, wf[3][2 * i + 1], ay1);
        }
        // ---- gate o tail (the only exposed one) ----
        float Po0, Po1;
        {
            float lo, hi;
            unpack2(add2(ax0, ay0), lo, hi); Po0 = lo + hi;
            unpack2(add2(ax1, ay1), lo, hi); Po1 = lo + hi;
        }
        float oo = k ? Po1 : Po0;
        float ro = __shfl_xor_sync(FULL, k ? Po0 : Po1, 1);
        float so = sigmoid_half(oo + ro);
        h_sh[cur ^ 1][k][u] = so * thc;
        #undef GATE_DOT
    };

    auto layer1_step = [&](int s) {          // computes layer-1 step s
        const int buf = (s + 1) & 1;         // h_sh[buf] holds h^{(0)}(s)
        const float* hv = h_sh[buf][l1b];
        float p0 = 0.f, p1 = 0.f;
        #pragma unroll
        for (int j = 0; j < 8; ++j) {
            p0 = fmaf(hv[l1bk + 4 * (2 * j)],     w1r[2 * j],     p0);
            p1 = fmaf(hv[l1bk + 4 * (2 * j + 1)], w1r[2 * j + 1], p1);
        }
        float p = p0 + p1;
        p += __shfl_xor_sync(FULL, p, 4);    // stays within 16-lane half
        p += __shfl_xor_sync(FULL, p, 8);
        float z1 = fmaf(h1, w1h, p + b1v);

        float zz = (l1g == 2) ? (z1 + 1.0f) : z1;
        // gate: j -> tanh(z); i/f/o -> sigma(z) = 0.5*tanh(z/2)+0.5
        float r = (l1g == 1) ? tanh_ap(zz)
                             : fmaf(0.5f, tanh_ap(0.5f * zz), 0.5f);

        float ri = __shfl_sync(FULL, r, 0, 4);
        float rj = __shfl_sync(FULL, r, 1, 4);
        float rf = __shfl_sync(FULL, r, 2, 4);
        float ro = __shfl_sync(FULL, r, 3, 4);
        c1 = fmaf(rf, c1, ri * rj);
        h1 = ro * tanh_ap(c1);
        if ((lane & 15) == 0)
            out[(2 * bb + l1b) * T + s] = fmaf(h1, wdv, bdv);
    };

    // ---- Peeled main sequence ----
    __syncthreads();                      // orders phase-0 writes + h init
    if (tid < 128) layer0_step(0);
    #pragma unroll 1
    for (int t = 1; t < T; ++t) {
        __syncthreads();                  // publishes h(t-1)
        if (tid < 128) layer0_step(t);
        else           layer1_step(t - 1);
    }
    __syncthreads();                      // publishes h(T-1)
    if (tid >= 128) layer1_step(T - 1);   // drain
}

extern "C" void kernel_launch(void* const* d_in, const int* in_sizes, int n_in,
                              void* d_out, int out_size) {
    const float* x  = (const float*)d_in[0];
    const float* W0 = (const float*)d_in[1];
    const float* b0 = (const float*)d_in[2];
    const float* W1 = (const float*)d_in[3];
    const float* b1 = (const float*)d_in[4];
    const float* Wd = (const float*)d_in[5];
    const float* bd = (const float*)d_in[6];
    float* out = (float*)d_out;
    lstm_stack_kernel<<<128, 160>>>(x, W0, b0, W1, b1, Wd, bd, out);
}